// round 3
// baseline (speedup 1.0000x reference)
#include <cuda_runtime.h>

#define NB       262144
#define THREADS  128
#define ROWS_PER_TILE 256           // 128 threads x 2 rows
#define NTILES   (NB / ROWS_PER_TILE)   // 1024
#define GRID_X   148

typedef unsigned long long u64;

// ---- packed f32x2 helpers (SASS FFMA2) ----
__device__ __forceinline__ u64 ffma2(u64 a, u64 b, u64 c) {
    u64 d;
    asm("fma.rn.f32x2 %0, %1, %2, %3;" : "=l"(d) : "l"(a), "l"(b), "l"(c));
    return d;
}
__device__ __forceinline__ u64 fadd2(u64 a, u64 b) {
    u64 d;
    asm("add.rn.f32x2 %0, %1, %2;" : "=l"(d) : "l"(a), "l"(b));
    return d;
}
__device__ __forceinline__ u64 pack2(float lo, float hi) {
    u64 d;
    asm("mov.b64 %0, {%1, %2};" : "=l"(d) : "f"(lo), "f"(hi));
    return d;
}
__device__ __forceinline__ void unpack2(u64 a, float& lo, float& hi) {
    asm("mov.b64 {%0, %1}, %2;" : "=f"(lo), "=f"(hi) : "l"(a));
}
__device__ __forceinline__ float hsum2(u64 a) {
    float lo, hi; unpack2(a, lo, hi); return lo + hi;
}

// ---- smem layout (u64 units) ----
// WfP [0,6144)      : forward pairs  WfP[l][k][p] = {W_l[2p][k+1],  W_l[2p+1][k+1]}
// WbP [6144,12288)  : backward pairs WbP[l][j][p] = {W_l[j][2p+1],  W_l[j][2p+2]}
// tcol[12288,12384) : {W_l[2p][0], W_l[2p+1][0]}
// bias[12384,12480) : float[3][64]
// scp [12480,20672) : u64[2][32][128] per-thread activation scratch columns
#define U64_WF   0
#define U64_WB   6144
#define U64_TC   12288
#define U64_BI   12384
#define U64_SC   12480
#define SMEM_BYTES (20672 * 8)     // 165,376 B

// Forward layer: bit-exact cublas-order chain per output.
// acc_j = fma(t, W[j][0], 0); then k ascending: acc_j = fma(h_k, W[j][k+1], acc_j).
// Shares weight loads between rows A and B.
__device__ __forceinline__ void mlp_pass(const u64* __restrict__ W,     // 64 x 32 pairs
                                         const u64* __restrict__ tc,    // 32 pairs or null
                                         u64 tt,
                                         const float* __restrict__ pA,  // this thread's scalar col, row A
                                         const float* __restrict__ pB,
                                         u64 (&accA)[32], u64 (&accB)[32])
{
#pragma unroll
    for (int p = 0; p < 32; ++p) {
        if (tc) {
            accA[p] = ffma2(tt, tc[p], 0ull);
            accB[p] = ffma2(tt, tc[p], 0ull);
        } else {
            accA[p] = 0ull; accB[p] = 0ull;
        }
    }
#pragma unroll 2
    for (int k = 0; k < 64; ++k) {
        const ulonglong2* wr = reinterpret_cast<const ulonglong2*>(W + k * 32);
        float hA = pA[(k >> 1) * 256 + (k & 1)];
        float hB = pB[(k >> 1) * 256 + (k & 1)];
        u64 hA2 = pack2(hA, hA);
        u64 hB2 = pack2(hB, hB);
#pragma unroll
        for (int q = 0; q < 16; ++q) {
            ulonglong2 w = wr[q];
            accA[2*q]   = ffma2(hA2, w.x, accA[2*q]);
            accA[2*q+1] = ffma2(hA2, w.y, accA[2*q+1]);
            accB[2*q]   = ffma2(hB2, w.x, accB[2*q]);
            accB[2*q+1] = ffma2(hB2, w.y, accB[2*q+1]);
        }
    }
}

__global__ void __launch_bounds__(THREADS, 1)
odefunc_kernel(const float* __restrict__ t_p,
               const float* __restrict__ z,
               const float* __restrict__ e,
               const float* __restrict__ W0g, const float* __restrict__ b0g,
               const float* __restrict__ W1g, const float* __restrict__ b1g,
               const float* __restrict__ W2g, const float* __restrict__ b2g,
               float* __restrict__ out)
{
    extern __shared__ __align__(16) u64 sm[];
    u64*   WfP = sm + U64_WF;
    u64*   WbP = sm + U64_WB;
    u64*   tcP = sm + U64_TC;
    float* Bf  = reinterpret_cast<float*>(sm + U64_BI);
    u64*   scA = sm + U64_SC;            // [32][128]
    u64*   scB = sm + U64_SC + 4096;     // [32][128]

    const int tid = threadIdx.x;
    const float t = t_p[0];

    // ---- one-time weight staging per persistent CTA ----
    {
        float* WfF = reinterpret_cast<float*>(WfP);
        float* WbF = reinterpret_cast<float*>(WbP);
        const float* Wg[3] = { W0g, W1g, W2g };
        const float* bg[3] = { b0g, b1g, b2g };
#pragma unroll 1
        for (int l = 0; l < 3; ++l) {
            for (int idx = tid; idx < 4096; idx += THREADS) {
                int j = idx >> 6, k = idx & 63;
                float w = Wg[l][j * 65 + k + 1];
                WfF[((l * 64 + k) * 32 + (j >> 1)) * 2 + (j & 1)] = w;
                WbF[((l * 64 + j) * 32 + (k >> 1)) * 2 + (k & 1)] = w;
            }
            if (tid < 64) {
                reinterpret_cast<float*>(tcP)[l * 64 + tid] = Wg[l][tid * 65];
                Bf[l * 64 + tid] = bg[l][tid];
            }
        }
    }
    __syncthreads();

    const u64 tt = pack2(t, t);
    float* pA = reinterpret_cast<float*>(scA) + tid * 2;
    float* pB = reinterpret_cast<float*>(scB) + tid * 2;
    u64 accA[32], accB[32];

    for (int tile = blockIdx.x; tile < NTILES; tile += gridDim.x) {
        const long rowA = (long)tile * ROWS_PER_TILE + tid;
        const long rowB = rowA + THREADS;

        // ---- stage z rows into private scratch columns ----
        {
            const ulonglong2* za = reinterpret_cast<const ulonglong2*>(z + rowA * 64);
            const ulonglong2* zb = reinterpret_cast<const ulonglong2*>(z + rowB * 64);
#pragma unroll
            for (int i = 0; i < 16; ++i) {
                ulonglong2 qa = za[i]; ulonglong2 qb = zb[i];
                scA[(2*i) * 128 + tid] = qa.x;  scA[(2*i+1) * 128 + tid] = qa.y;
                scB[(2*i) * 128 + tid] = qb.x;  scB[(2*i+1) * 128 + tid] = qb.y;
            }
        }

        u64 mA0, mA1, mB0, mB1;

        // ---- forward L0, L1 (relu) ----
#pragma unroll 1
        for (int l = 0; l < 2; ++l) {
            mlp_pass(WfP + l * 2048, tcP + l * 32, tt, pA, pB, accA, accB);
            const float* bL = Bf + l * 64;
            u64 mA = 0ull, mB = 0ull;
#pragma unroll
            for (int p = 0; p < 32; ++p) {
                float a0, a1, c0, c1;
                unpack2(accA[p], a0, a1);
                unpack2(accB[p], c0, c1);
                a0 += bL[2*p]; a1 += bL[2*p+1];
                c0 += bL[2*p]; c1 += bL[2*p+1];
                mA |= (u64)(a0 > 0.0f) << (2*p);
                mA |= (u64)(a1 > 0.0f) << (2*p+1);
                mB |= (u64)(c0 > 0.0f) << (2*p);
                mB |= (u64)(c1 > 0.0f) << (2*p+1);
                scA[p * 128 + tid] = pack2(fmaxf(a0, 0.0f), fmaxf(a1, 0.0f));
                scB[p * 128 + tid] = pack2(fmaxf(c0, 0.0f), fmaxf(c1, 0.0f));
            }
            if (l == 0) { mA0 = mA; mB0 = mB; } else { mA1 = mA; mB1 = mB; }
        }

        // ---- forward L2 (linear) -> z_dot ----
        mlp_pass(WfP + 2 * 2048, tcP + 2 * 32, tt, pA, pB, accA, accB);
        {
            const float* bL = Bf + 2 * 64;
            u64* oA = reinterpret_cast<u64*>(out + rowA * 64);
            u64* oB = reinterpret_cast<u64*>(out + rowB * 64);
#pragma unroll
            for (int p = 0; p < 32; ++p) {
                float a0, a1, c0, c1;
                unpack2(accA[p], a0, a1);
                unpack2(accB[p], c0, c1);
                oA[p] = pack2(a0 + bL[2*p], a1 + bL[2*p+1]);
                oB[p] = pack2(c0 + bL[2*p], c1 + bL[2*p+1]);
            }
        }

        // ---- stage e rows into scratch (cotangent) ----
        {
            const ulonglong2* ea = reinterpret_cast<const ulonglong2*>(e + rowA * 64);
            const ulonglong2* eb = reinterpret_cast<const ulonglong2*>(e + rowB * 64);
#pragma unroll
            for (int i = 0; i < 16; ++i) {
                ulonglong2 qa = ea[i]; ulonglong2 qb = eb[i];
                scA[(2*i) * 128 + tid] = qa.x;  scA[(2*i+1) * 128 + tid] = qa.y;
                scB[(2*i) * 128 + tid] = qb.x;  scB[(2*i+1) * 128 + tid] = qb.y;
            }
        }

        // ---- backward B2: a1 = mask1 .* (W2'^T e) ----
        mlp_pass(WbP + 2 * 2048, nullptr, tt, pA, pB, accA, accB);
#pragma unroll
        for (int p = 0; p < 32; ++p) {
            float a0, a1, c0, c1;
            unpack2(accA[p], a0, a1);
            unpack2(accB[p], c0, c1);
            a0 = ((mA1 >> (2*p)) & 1ull)   ? a0 : 0.0f;
            a1 = ((mA1 >> (2*p+1)) & 1ull) ? a1 : 0.0f;
            c0 = ((mB1 >> (2*p)) & 1ull)   ? c0 : 0.0f;
            c1 = ((mB1 >> (2*p+1)) & 1ull) ? c1 : 0.0f;
            scA[p * 128 + tid] = pack2(a0, a1);
            scB[p * 128 + tid] = pack2(c0, c1);
        }

        // ---- backward B1: a0 = mask0 .* (W1'^T a1) ----
        mlp_pass(WbP + 1 * 2048, nullptr, tt, pA, pB, accA, accB);
#pragma unroll
        for (int p = 0; p < 32; ++p) {
            float a0, a1, c0, c1;
            unpack2(accA[p], a0, a1);
            unpack2(accB[p], c0, c1);
            a0 = ((mA0 >> (2*p)) & 1ull)   ? a0 : 0.0f;
            a1 = ((mA0 >> (2*p+1)) & 1ull) ? a1 : 0.0f;
            c0 = ((mB0 >> (2*p)) & 1ull)   ? c0 : 0.0f;
            c1 = ((mB0 >> (2*p+1)) & 1ull) ? c1 : 0.0f;
            scA[p * 128 + tid] = pack2(a0, a1);
            scB[p * 128 + tid] = pack2(c0, c1);
        }

        // ---- backward B0: gin = W0'^T a0 ; div = dot(gin, e) ----
        mlp_pass(WbP + 0 * 2048, nullptr, tt, pA, pB, accA, accB);
        {
            const ulonglong2* ea = reinterpret_cast<const ulonglong2*>(e + rowA * 64);
            const ulonglong2* eb = reinterpret_cast<const ulonglong2*>(e + rowB * 64);
            u64 dA0 = 0ull, dA1 = 0ull, dB0 = 0ull, dB1 = 0ull;
#pragma unroll
            for (int i = 0; i < 16; ++i) {
                ulonglong2 qa = ea[i]; ulonglong2 qb = eb[i];
                dA0 = ffma2(qa.x, accA[2*i],   dA0);
                dA1 = ffma2(qa.y, accA[2*i+1], dA1);
                dB0 = ffma2(qb.x, accB[2*i],   dB0);
                dB1 = ffma2(qb.y, accB[2*i+1], dB1);
            }
            out[(long)NB * 64 + rowA] = -hsum2(fadd2(dA0, dA1));
            out[(long)NB * 64 + rowB] = -hsum2(fadd2(dB0, dB1));
        }
    }
}

extern "C" void kernel_launch(void* const* d_in, const int* in_sizes, int n_in,
                              void* d_out, int out_size) {
    const float* t  = (const float*)d_in[0];
    const float* z  = (const float*)d_in[1];
    const float* e  = (const float*)d_in[2];
    const float* W0 = (const float*)d_in[3];
    const float* b0 = (const float*)d_in[4];
    const float* W1 = (const float*)d_in[5];
    const float* b1 = (const float*)d_in[6];
    const float* W2 = (const float*)d_in[7];
    const float* b2 = (const float*)d_in[8];
    float* out = (float*)d_out;

    cudaFuncSetAttribute(odefunc_kernel,
                         cudaFuncAttributeMaxDynamicSharedMemorySize, SMEM_BYTES);

    odefunc_kernel<<<GRID_X, THREADS, SMEM_BYTES>>>(t, z, e, W0, b0, W1, b1, W2, b2, out);
}

// round 6
// speedup vs baseline: 1.3244x; 1.3244x over previous
#include <cuda_runtime.h>

#define NB       262144
#define THREADS  256
#define ROWS_PER_TILE 256
#define NTILES   (NB / ROWS_PER_TILE)   // 1024
#define GRID_X   148

typedef unsigned long long u64;

// ---- packed f32x2 helpers (SASS FFMA2) ----
__device__ __forceinline__ u64 ffma2(u64 a, u64 b, u64 c) {
    u64 d;
    asm("fma.rn.f32x2 %0, %1, %2, %3;" : "=l"(d) : "l"(a), "l"(b), "l"(c));
    return d;
}
__device__ __forceinline__ u64 fadd2(u64 a, u64 b) {
    u64 d;
    asm("add.rn.f32x2 %0, %1, %2;" : "=l"(d) : "l"(a), "l"(b));
    return d;
}
__device__ __forceinline__ u64 pack2(float lo, float hi) {
    u64 d;
    asm("mov.b64 %0, {%1, %2};" : "=l"(d) : "f"(lo), "f"(hi));
    return d;
}
__device__ __forceinline__ void unpack2(u64 a, float& lo, float& hi) {
    asm("mov.b64 {%0, %1}, %2;" : "=f"(lo), "=f"(hi) : "l"(a));
}
__device__ __forceinline__ float hsum2(u64 a) {
    float lo, hi; unpack2(a, lo, hi); return lo + hi;
}

// ---- smem layout (u64 units) ----
// WfP [0,6144)      : forward  pairs WfP[l][k][p] = {W_l[2p][k+1],   W_l[2p+1][k+1]}   (pairs over output j)
// WbP [6144,12288)  : backward pairs WbP[l][j][p] = {W_l[j][2p+1],   W_l[j][2p+2]}     (pairs over input k)
// tcP [12288,12384) : t-col pairs    tcP[l][p]    = {W_l[2p][0],     W_l[2p+1][0]}
// bias[12384,12480) : float[3][64] = 768 B = 96 u64   (R5 bug: had reserved only 24 u64)
#define U_WF  0
#define U_WB  6144
#define U_TC  12288
#define U_BI  12384
#define SMEM_BYTES (12480 * 8)   // 99,840 B

// Forward layer: bit-exact cublas-order chain per output j:
//   acc_j = fma(t, W[j][0], 0); for k=0..63 ascending: acc_j = fma(h_k, W[j][k+1], acc_j)
// 16 LDS.128 + 32 FFMA2 per k; h in registers (static indices, fully unrolled).
__device__ __forceinline__ void fwd_pass(const u64* __restrict__ W,
                                         const u64* __restrict__ tc,
                                         u64 tt, const float (&h)[64], u64 (&acc)[32])
{
    const ulonglong2* tp = reinterpret_cast<const ulonglong2*>(tc);
#pragma unroll
    for (int q = 0; q < 16; ++q) {
        ulonglong2 tw = tp[q];
        acc[2*q]   = ffma2(tt, tw.x, 0ull);
        acc[2*q+1] = ffma2(tt, tw.y, 0ull);
    }
#pragma unroll
    for (int k = 0; k < 64; ++k) {
        u64 hh = pack2(h[k], h[k]);
        const ulonglong2* wr = reinterpret_cast<const ulonglong2*>(W + k * 32);
#pragma unroll
        for (int q = 0; q < 16; ++q) {
            ulonglong2 w = wr[q];
            acc[2*q]   = ffma2(hh, w.x, acc[2*q]);
            acc[2*q+1] = ffma2(hh, w.y, acc[2*q+1]);
        }
    }
}

// Backward layer: acc_k = sum_j g_j * W[j][k+1]  (order-free), same load shape.
__device__ __forceinline__ void bwd_pass(const u64* __restrict__ W,
                                         const float (&g)[64], u64 (&acc)[32])
{
#pragma unroll
    for (int p = 0; p < 32; ++p) acc[p] = 0ull;
#pragma unroll
    for (int j = 0; j < 64; ++j) {
        u64 gg = pack2(g[j], g[j]);
        const ulonglong2* wr = reinterpret_cast<const ulonglong2*>(W + j * 32);
#pragma unroll
        for (int q = 0; q < 16; ++q) {
            ulonglong2 w = wr[q];
            acc[2*q]   = ffma2(gg, w.x, acc[2*q]);
            acc[2*q+1] = ffma2(gg, w.y, acc[2*q+1]);
        }
    }
}

__global__ void __launch_bounds__(THREADS, 1)
odefunc_kernel(const float* __restrict__ t_p,
               const float* __restrict__ z,
               const float* __restrict__ e,
               const float* __restrict__ W0g, const float* __restrict__ b0g,
               const float* __restrict__ W1g, const float* __restrict__ b1g,
               const float* __restrict__ W2g, const float* __restrict__ b2g,
               float* __restrict__ out)
{
    extern __shared__ __align__(16) u64 sm[];
    u64*   WfP = sm + U_WF;
    u64*   WbP = sm + U_WB;
    u64*   tcP = sm + U_TC;
    float* Bf  = reinterpret_cast<float*>(sm + U_BI);

    const int tid = threadIdx.x;
    const float t = t_p[0];

    // ---- one-time weight staging per persistent CTA ----
    {
        float* WfF = reinterpret_cast<float*>(WfP);
        float* WbF = reinterpret_cast<float*>(WbP);
        float* tcF = reinterpret_cast<float*>(tcP);
        const float* Wg[3] = { W0g, W1g, W2g };
        const float* bg[3] = { b0g, b1g, b2g };
#pragma unroll 1
        for (int l = 0; l < 3; ++l) {
            for (int idx = tid; idx < 4096; idx += THREADS) {
                int j = idx >> 6, k = idx & 63;
                float w = Wg[l][j * 65 + k + 1];
                WfF[((l * 64 + k) * 32 + (j >> 1)) * 2 + (j & 1)] = w;
                WbF[((l * 64 + j) * 32 + (k >> 1)) * 2 + (k & 1)] = w;
            }
            if (tid < 64) {
                tcF[(l * 32 + (tid >> 1)) * 2 + (tid & 1)] = Wg[l][tid * 65];
                Bf[l * 64 + tid] = bg[l][tid];
            }
        }
    }
    __syncthreads();

    const u64 tt = pack2(t, t);
    float h[64];
    u64 acc[32];

    for (int tile = blockIdx.x; tile < NTILES; tile += GRID_X) {
        const size_t row = (size_t)tile * ROWS_PER_TILE + tid;

        // ---- load z row into registers ----
        {
            const float4* zp = reinterpret_cast<const float4*>(z + row * 64);
#pragma unroll
            for (int i = 0; i < 16; ++i) {
                float4 q = zp[i];
                h[4*i] = q.x; h[4*i+1] = q.y; h[4*i+2] = q.z; h[4*i+3] = q.w;
            }
        }

        u64 m0 = 0ull, m1 = 0ull;

        // ---- forward L0 (relu) ----
        fwd_pass(WfP + 0 * 2048, tcP + 0 * 32, tt, h, acc);
        {
            const float* bL = Bf + 0 * 64;
#pragma unroll
            for (int p = 0; p < 32; ++p) {
                float v0, v1; unpack2(acc[p], v0, v1);
                v0 += bL[2*p]; v1 += bL[2*p+1];
                m0 |= (u64)(v0 > 0.0f) << (2*p);
                m0 |= (u64)(v1 > 0.0f) << (2*p+1);
                h[2*p]   = fmaxf(v0, 0.0f);
                h[2*p+1] = fmaxf(v1, 0.0f);
            }
        }

        // ---- forward L1 (relu) ----
        fwd_pass(WfP + 1 * 2048, tcP + 1 * 32, tt, h, acc);
        {
            const float* bL = Bf + 1 * 64;
#pragma unroll
            for (int p = 0; p < 32; ++p) {
                float v0, v1; unpack2(acc[p], v0, v1);
                v0 += bL[2*p]; v1 += bL[2*p+1];
                m1 |= (u64)(v0 > 0.0f) << (2*p);
                m1 |= (u64)(v1 > 0.0f) << (2*p+1);
                h[2*p]   = fmaxf(v0, 0.0f);
                h[2*p+1] = fmaxf(v1, 0.0f);
            }
        }

        // ---- forward L2 (linear) -> z_dot ----
        fwd_pass(WfP + 2 * 2048, tcP + 2 * 32, tt, h, acc);
        {
            const float* bL = Bf + 2 * 64;
            float4* o4 = reinterpret_cast<float4*>(out + row * 64);
#pragma unroll
            for (int q = 0; q < 16; ++q) {
                float v0, v1, v2, v3;
                unpack2(acc[2*q],   v0, v1);
                unpack2(acc[2*q+1], v2, v3);
                o4[q] = make_float4(v0 + bL[4*q],   v1 + bL[4*q+1],
                                    v2 + bL[4*q+2], v3 + bL[4*q+3]);
            }
        }

        // ---- load e row into registers (cotangent) ----
        {
            const float4* ep = reinterpret_cast<const float4*>(e + row * 64);
#pragma unroll
            for (int i = 0; i < 16; ++i) {
                float4 q = ep[i];
                h[4*i] = q.x; h[4*i+1] = q.y; h[4*i+2] = q.z; h[4*i+3] = q.w;
            }
        }

        // ---- backward B2: a1 = mask1 .* (W2'^T e) ----
        bwd_pass(WbP + 2 * 2048, h, acc);
#pragma unroll
        for (int p = 0; p < 32; ++p) {
            float v0, v1; unpack2(acc[p], v0, v1);
            h[2*p]   = ((m1 >> (2*p))   & 1ull) ? v0 : 0.0f;
            h[2*p+1] = ((m1 >> (2*p+1)) & 1ull) ? v1 : 0.0f;
        }

        // ---- backward B1: a0 = mask0 .* (W1'^T a1) ----
        bwd_pass(WbP + 1 * 2048, h, acc);
#pragma unroll
        for (int p = 0; p < 32; ++p) {
            float v0, v1; unpack2(acc[p], v0, v1);
            h[2*p]   = ((m0 >> (2*p))   & 1ull) ? v0 : 0.0f;
            h[2*p+1] = ((m0 >> (2*p+1)) & 1ull) ? v1 : 0.0f;
        }

        // ---- backward B0: gin = W0'^T a0 ; div = dot(gin, e) fused ----
        bwd_pass(WbP + 0 * 2048, h, acc);
        {
            const ulonglong2* er = reinterpret_cast<const ulonglong2*>(e + row * 64);
            u64 d0 = 0ull, d1 = 0ull;
#pragma unroll
            for (int q = 0; q < 16; ++q) {
                ulonglong2 eq = er[q];
                d0 = ffma2(eq.x, acc[2*q],   d0);
                d1 = ffma2(eq.y, acc[2*q+1], d1);
            }
            out[(size_t)NB * 64 + row] = -hsum2(fadd2(d0, d1));
        }
    }
}

extern "C" void kernel_launch(void* const* d_in, const int* in_sizes, int n_in,
                              void* d_out, int out_size) {
    const float* t  = (const float*)d_in[0];
    const float* z  = (const float*)d_in[1];
    const float* e  = (const float*)d_in[2];
    const float* W0 = (const float*)d_in[3];
    const float* b0 = (const float*)d_in[4];
    const float* W1 = (const float*)d_in[5];
    const float* b1 = (const float*)d_in[6];
    const float* W2 = (const float*)d_in[7];
    const float* b2 = (const float*)d_in[8];
    float* out = (float*)d_out;

    cudaFuncSetAttribute(odefunc_kernel,
                         cudaFuncAttributeMaxDynamicSharedMemorySize, SMEM_BYTES);

    odefunc_kernel<<<GRID_X, THREADS, SMEM_BYTES>>>(t, z, e, W0, b0, W1, b1, W2, b2, out);
}

// round 7
// speedup vs baseline: 1.5625x; 1.1797x over previous
#include <cuda_runtime.h>

#define NB       262144
#define THREADS  256
#define ROWS_PER_TILE 256
#define NTILES   (NB / ROWS_PER_TILE)   // 1024
#define GRID_X   148

typedef unsigned long long u64;

// ---- packed f32x2 helpers (SASS FFMA2) ----
__device__ __forceinline__ u64 ffma2(u64 a, u64 b, u64 c) {
    u64 d;
    asm("fma.rn.f32x2 %0, %1, %2, %3;" : "=l"(d) : "l"(a), "l"(b), "l"(c));
    return d;
}
__device__ __forceinline__ u64 fadd2(u64 a, u64 b) {
    u64 d;
    asm("add.rn.f32x2 %0, %1, %2;" : "=l"(d) : "l"(a), "l"(b));
    return d;
}
__device__ __forceinline__ u64 pack2(float lo, float hi) {
    u64 d;
    asm("mov.b64 %0, {%1, %2};" : "=l"(d) : "f"(lo), "f"(hi));
    return d;
}
__device__ __forceinline__ void unpack2(u64 a, float& lo, float& hi) {
    asm("mov.b64 {%0, %1}, %2;" : "=f"(lo), "=f"(hi) : "l"(a));
}
__device__ __forceinline__ float hsum2(u64 a) {
    float lo, hi; unpack2(a, lo, hi); return lo + hi;
}

// ---- smem layout (u64 units) ----
// WfP [0,6144)      : forward  pairs WfP[l][k][p] = {W_l[2p][k+1], W_l[2p+1][k+1]}
// WbP [6144,12288)  : backward pairs WbP[l][j][p] = {W_l[j][2p+1], W_l[j][2p+2]}
// tcP [12288,12384) : t-col pairs    tcP[l][p]    = {W_l[2p][0],   W_l[2p+1][0]}
// bias[12384,12480) : float[3][64] = 768 B = 96 u64
#define U_WF  0
#define U_WB  6144
#define U_TC  12288
#define U_BI  12384
#define SMEM_BYTES (12480 * 8)   // 99,840 B

__global__ void __launch_bounds__(THREADS, 1)
odefunc_kernel(const float* __restrict__ t_p,
               const float* __restrict__ z,
               const float* __restrict__ e,
               const float* __restrict__ W0g, const float* __restrict__ b0g,
               const float* __restrict__ W1g, const float* __restrict__ b1g,
               const float* __restrict__ W2g, const float* __restrict__ b2g,
               float* __restrict__ out)
{
    extern __shared__ __align__(16) u64 sm[];
    u64*   tcP = sm + U_TC;
    float* Bf  = reinterpret_cast<float*>(sm + U_BI);

    const int tid = threadIdx.x;
    const float t = t_p[0];

    // ---- one-time weight staging per persistent CTA ----
    {
        float* WfF = reinterpret_cast<float*>(sm + U_WF);
        float* WbF = reinterpret_cast<float*>(sm + U_WB);
        float* tcF = reinterpret_cast<float*>(tcP);
        const float* Wg[3] = { W0g, W1g, W2g };
        const float* bg[3] = { b0g, b1g, b2g };
#pragma unroll 1
        for (int l = 0; l < 3; ++l) {
            for (int idx = tid; idx < 4096; idx += THREADS) {
                int j = idx >> 6, k = idx & 63;
                float w = Wg[l][j * 65 + k + 1];
                WfF[((l * 64 + k) * 32 + (j >> 1)) * 2 + (j & 1)] = w;
                WbF[((l * 64 + j) * 32 + (k >> 1)) * 2 + (k & 1)] = w;
            }
            if (tid < 64) {
                tcF[(l * 32 + (tid >> 1)) * 2 + (tid & 1)] = Wg[l][tid * 65];
                Bf[l * 64 + tid] = bg[l][tid];
            }
        }
    }
    __syncthreads();

    const u64 tt = pack2(t, t);
    float h[64];
    u64 acc[32];

    for (int tile = blockIdx.x; tile < NTILES; tile += GRID_X) {
        const size_t row = (size_t)tile * ROWS_PER_TILE + tid;

        // ---- load z row into registers ----
        {
            const float4* zp = reinterpret_cast<const float4*>(z + row * 64);
#pragma unroll
            for (int i = 0; i < 16; ++i) {
                float4 q = zp[i];
                h[4*i] = q.x; h[4*i+1] = q.y; h[4*i+2] = q.z; h[4*i+3] = q.w;
            }
        }

        u64 m0 = 0ull, m1 = 0ull;

        // ---- six passes share ONE rolled body (liveness barrier per pass) ----
        // pass 0,1,2 : forward L0,L1,L2 (bit-exact cublas-order chains)
        // pass 3,4,5 : backward B2,B1,B0
#pragma unroll 1
        for (int pass = 0; pass < 6; ++pass) {
            const u64* W = sm + ((pass < 3) ? (U_WF + pass * 2048)
                                            : (U_WB + (5 - pass) * 2048));

            // init accumulators
            if (pass < 3) {
                const ulonglong2* tp = reinterpret_cast<const ulonglong2*>(tcP + pass * 32);
#pragma unroll
                for (int q = 0; q < 16; ++q) {
                    ulonglong2 tw = tp[q];
                    acc[2*q]   = ffma2(tt, tw.x, 0ull);   // k=0 term: t * W[:,0]
                    acc[2*q+1] = ffma2(tt, tw.y, 0ull);
                }
            } else {
#pragma unroll
                for (int p = 0; p < 32; ++p) acc[p] = 0ull;
            }

            // serial-k / serial-j chain: 16 LDS.128 + 32 FFMA2 per step
#pragma unroll
            for (int k = 0; k < 64; ++k) {
                u64 hh = pack2(h[k], h[k]);
                const ulonglong2* wr = reinterpret_cast<const ulonglong2*>(W + k * 32);
#pragma unroll
                for (int q = 0; q < 16; ++q) {
                    ulonglong2 w = wr[q];
                    acc[2*q]   = ffma2(hh, w.x, acc[2*q]);
                    acc[2*q+1] = ffma2(hh, w.y, acc[2*q+1]);
                }
            }

            // epilogues
            if (pass < 2) {
                // relu + mask, bias added once (matches reference bit-for-bit)
                const float* bL = Bf + pass * 64;
                u64 m = 0ull;
#pragma unroll
                for (int p = 0; p < 32; ++p) {
                    float v0, v1; unpack2(acc[p], v0, v1);
                    v0 += bL[2*p]; v1 += bL[2*p+1];
                    m |= (u64)(v0 > 0.0f) << (2*p);
                    m |= (u64)(v1 > 0.0f) << (2*p+1);
                    h[2*p]   = fmaxf(v0, 0.0f);
                    h[2*p+1] = fmaxf(v1, 0.0f);
                }
                if (pass == 0) m0 = m; else m1 = m;
            } else if (pass == 2) {
                // z_dot out, then load cotangent e into h
                const float* bL = Bf + 2 * 64;
                float4* o4 = reinterpret_cast<float4*>(out + row * 64);
#pragma unroll
                for (int q = 0; q < 16; ++q) {
                    float v0, v1, v2, v3;
                    unpack2(acc[2*q],   v0, v1);
                    unpack2(acc[2*q+1], v2, v3);
                    o4[q] = make_float4(v0 + bL[4*q],   v1 + bL[4*q+1],
                                        v2 + bL[4*q+2], v3 + bL[4*q+3]);
                }
                const float4* ep = reinterpret_cast<const float4*>(e + row * 64);
#pragma unroll
                for (int i = 0; i < 16; ++i) {
                    float4 q = ep[i];
                    h[4*i] = q.x; h[4*i+1] = q.y; h[4*i+2] = q.z; h[4*i+3] = q.w;
                }
            } else if (pass < 5) {
                // relu-mask application
                u64 msel = (pass == 3) ? m1 : m0;
#pragma unroll
                for (int p = 0; p < 32; ++p) {
                    float v0, v1; unpack2(acc[p], v0, v1);
                    h[2*p]   = ((msel >> (2*p))   & 1ull) ? v0 : 0.0f;
                    h[2*p+1] = ((msel >> (2*p+1)) & 1ull) ? v1 : 0.0f;
                }
            } else {
                // gin = W0'^T a0 in acc; div = dot(gin, e) fused (e reload, L1-hot)
                const ulonglong2* er = reinterpret_cast<const ulonglong2*>(e + row * 64);
                u64 d0 = 0ull, d1 = 0ull;
#pragma unroll
                for (int q = 0; q < 16; ++q) {
                    ulonglong2 eq = er[q];
                    d0 = ffma2(eq.x, acc[2*q],   d0);
                    d1 = ffma2(eq.y, acc[2*q+1], d1);
                }
                out[(size_t)NB * 64 + row] = -hsum2(fadd2(d0, d1));
            }
        }
    }
}

extern "C" void kernel_launch(void* const* d_in, const int* in_sizes, int n_in,
                              void* d_out, int out_size) {
    const float* t  = (const float*)d_in[0];
    const float* z  = (const float*)d_in[1];
    const float* e  = (const float*)d_in[2];
    const float* W0 = (const float*)d_in[3];
    const float* b0 = (const float*)d_in[4];
    const float* W1 = (const float*)d_in[5];
    const float* b1 = (const float*)d_in[6];
    const float* W2 = (const float*)d_in[7];
    const float* b2 = (const float*)d_in[8];
    float* out = (float*)d_out;

    cudaFuncSetAttribute(odefunc_kernel,
                         cudaFuncAttributeMaxDynamicSharedMemorySize, SMEM_BYTES);

    odefunc_kernel<<<GRID_X, THREADS, SMEM_BYTES>>>(t, z, e, W0, b0, W1, b1, W2, b2, out);
}